// round 11
// baseline (speedup 1.0000x reference)
#include <cuda_runtime.h>
#include <cuda_bf16.h>
#include <math.h>
#include <stdint.h>

// Problem constants
#define BB 16
#define DD 128
#define LL 4096
#define NCH 64          // 64-token chunks per batch

// ---------------- scratch ----------------
__device__ float g_xspre[BB * DD * LL];
__device__ float g_z    [BB * DD * LL];
__device__ float g_S    [BB * DD * LL];
__device__ float g_yloc [BB * DD * LL];
__device__ float g_Cm   [BB * LL * 2];
__device__ float g_sumdt[BB * NCH * DD];
__device__ float g_hend [BB * NCH * DD * 2];
__device__ float g_h0   [BB * NCH * DD * 2];

// packed, pre-swizzled bf16 tiles (16B-aligned via uint4)
__device__ uint4 gW1[2][2][2][1024];   // W_in : [E-half][k-half][hi/lo] 16KB tiles (128 e x 32 dp)
__device__ uint4 gW3[2][2][1024];      // W_out: [k-half][hi/lo] 16KB tiles
__device__ uint4 gXhi[BB * NCH * 2 * 512];  // x^T: per (b,chunk,k-half) 8KB tiles (64 l x 32 dp)
__device__ uint4 gXlo[BB * NCH * 2 * 512];

// ---------------- helpers ----------------
__device__ __forceinline__ uint32_t smem_u32(const void* p) {
    uint32_t a;
    asm("{ .reg .u64 t; cvta.to.shared.u64 t, %1; cvt.u32.u64 %0, t; }" : "=r"(a) : "l"(p));
    return a;
}
__device__ __forceinline__ void ldsm4(uint32_t addr, uint32_t* r) {
    asm volatile("ldmatrix.sync.aligned.m8n8.x4.shared.b16 {%0,%1,%2,%3}, [%4];"
        : "=r"(r[0]), "=r"(r[1]), "=r"(r[2]), "=r"(r[3]) : "r"(addr));
}
__device__ __forceinline__ void mma_bf16(float* c, const uint32_t* a, uint32_t b0, uint32_t b1) {
    asm volatile("mma.sync.aligned.m16n8k16.row.col.f32.bf16.bf16.f32 "
        "{%0,%1,%2,%3}, {%4,%5,%6,%7}, {%8,%9}, {%0,%1,%2,%3};"
        : "+f"(c[0]), "+f"(c[1]), "+f"(c[2]), "+f"(c[3])
        : "r"(a[0]), "r"(a[1]), "r"(a[2]), "r"(a[3]), "r"(b0), "r"(b1));
}
__device__ __forceinline__ uint32_t pack_bf2(float a, float b) {
    __nv_bfloat16 ha = __float2bfloat16(a), hb = __float2bfloat16(b);
    return (uint32_t)__bfloat16_as_ushort(ha) | ((uint32_t)__bfloat16_as_ushort(hb) << 16);
}
__device__ __forceinline__ void split_pack(float v0, float v1, uint32_t& hi, uint32_t& lo) {
    __nv_bfloat16 h0 = __float2bfloat16(v0), h1 = __float2bfloat16(v1);
    hi = (uint32_t)__bfloat16_as_ushort(h0) | ((uint32_t)__bfloat16_as_ushort(h1) << 16);
    lo = pack_bf2(v0 - __bfloat162float(h0), v1 - __bfloat162float(h1));
}
#define SWZ(o) ((o) ^ ((((o) >> 7) & 7) << 4))
#define CP16(dst, src) asm volatile("cp.async.cg.shared.global [%0], [%1], 16;" :: "r"(dst), "l"(src))
#define CP_COMMIT()  asm volatile("cp.async.commit_group;" ::: "memory")
#define CP_WAIT0()   asm volatile("cp.async.wait_group 0;" ::: "memory")

// ================= K0w: pack weights into swizzled bf16 hi/lo tiles =================
__global__ __launch_bounds__(256) void k0w(const float* __restrict__ W_in,
                                           const float* __restrict__ W_out)
{
    const int tid = threadIdx.x;
    // W_in: 256 rows x 64 pairs
    for (int j = tid; j < 256 * 64; j += 256) {
        int e = j >> 6, dp = j & 63;
        int E = e >> 7, eL = e & 127, kh = dp >> 5, dpL = dp & 31;
        float2 w = *(const float2*)(W_in + (size_t)e * 128 + dp * 2);
        uint32_t hi, lo; split_pack(w.x, w.y, hi, lo);
        uint32_t off = SWZ((uint32_t)eL * 128u + (uint32_t)dpL * 4u);
        *(uint32_t*)((uint8_t*)gW1[E][kh][0] + off) = hi;
        *(uint32_t*)((uint8_t*)gW1[E][kh][1] + off) = lo;
    }
    // W_out: 128 rows x 64 pairs
    for (int j = tid; j < 128 * 64; j += 256) {
        int o = j >> 6, dp = j & 63;
        int kh = dp >> 5, dpL = dp & 31;
        float2 w = *(const float2*)(W_out + (size_t)o * 128 + dp * 2);
        uint32_t hi, lo; split_pack(w.x, w.y, hi, lo);
        uint32_t off = SWZ((uint32_t)o * 128u + (uint32_t)dpL * 4u);
        *(uint32_t*)((uint8_t*)gW3[kh][0] + off) = hi;
        *(uint32_t*)((uint8_t*)gW3[kh][1] + off) = lo;
    }
}

// ================= K0x: transpose+split x into swizzled tiles =================
// grid 2048 = (b*64+c)*2+h ; 128 threads; smem transpose for coalescing
__global__ __launch_bounds__(128) void k0x(const float* __restrict__ x1)
{
    __shared__ float sx[64 * 65];
    const int tid = threadIdx.x;
    const int bid = blockIdx.x;
    const int b = bid >> 7, c = (bid >> 1) & 63, h = bid & 1;
    const float* src = x1 + (size_t)b * DD * LL + (size_t)(h * 64) * LL + c * 64;

    // load 64 d x 64 l, coalesced along l
#pragma unroll 8
    for (int j = tid; j < 4096; j += 128) {
        int l = j & 63, di = j >> 6;
        sx[di * 65 + l] = src[(size_t)di * LL + l];
    }
    __syncthreads();

    uint8_t* dhi = (uint8_t*)(gXhi + (size_t)bid * 512);
    uint8_t* dlo = (uint8_t*)(gXlo + (size_t)bid * 512);
#pragma unroll 8
    for (int g = tid; g < 2048; g += 128) {
        int l = g >> 5, dpL = g & 31;
        float v0 = sx[(dpL * 2) * 65 + l];
        float v1 = sx[(dpL * 2 + 1) * 65 + l];
        uint32_t hi, lo; split_pack(v0, v1, hi, lo);
        uint32_t off = SWZ((uint32_t)l * 128u + (uint32_t)dpL * 4u);
        *(uint32_t*)(dhi + off) = hi;
        *(uint32_t*)(dlo + off) = lo;
    }
}

// ================= K1: xz = x @ W_in^T =================
// grid (1024, 2): 64 tokens x 128 outputs, 128 threads, 4 CTAs/SM
#define K1_TAH 0
#define K1_TAL 8192
#define K1_TBH 16384
#define K1_TBL 32768
#define K1_SMEM 49152

__global__ __launch_bounds__(128, 4) void k1_mma()
{
    extern __shared__ char smem[];
    const uint32_t sb = smem_u32(smem);
    const int tid = threadIdx.x, wid = tid >> 5, lane = tid & 31;
    const int b = blockIdx.x >> 6;
    const int c = blockIdx.x & 63;
    const int l0 = c << 6;
    const int E = blockIdx.y;

    const int m0 = (wid & 1) * 32, n0 = (wid >> 1) * 64;
    const int rsel = lane & 15;
    const int csel = (lane >> 4) * 8;

    float acc[2][8][4];
#pragma unroll
    for (int mt = 0; mt < 2; mt++)
#pragma unroll
        for (int nt = 0; nt < 8; nt++)
#pragma unroll
            for (int q = 0; q < 4; q++) acc[mt][nt][q] = 0.f;

#pragma unroll 1
    for (int h = 0; h < 2; h++) {
        if (h) __syncthreads();
        const uint4* pXh = gXhi + (size_t)(((b * NCH + c) * 2) + h) * 512;
        const uint4* pXl = gXlo + (size_t)(((b * NCH + c) * 2) + h) * 512;
        const uint4* pBh = gW1[E][h][0];
        const uint4* pBl = gW1[E][h][1];
#pragma unroll 4
        for (int j = tid; j < 512; j += 128) {
            CP16(sb + K1_TAH + j * 16, pXh + j);
            CP16(sb + K1_TAL + j * 16, pXl + j);
        }
#pragma unroll 8
        for (int j = tid; j < 1024; j += 128) {
            CP16(sb + K1_TBH + j * 16, pBh + j);
            CP16(sb + K1_TBL + j * 16, pBl + j);
        }
        CP_COMMIT();
        CP_WAIT0();
        __syncthreads();

#pragma unroll 1
        for (int term = 0; term < 3; term++) {
            uint32_t ab = sb + (term == 2 ? K1_TAL : K1_TAH);
            uint32_t bb = sb + (term == 1 ? K1_TBL : K1_TBH);
#pragma unroll
            for (int ks = 0; ks < 4; ks++) {
                uint32_t kc = (uint32_t)(ks * 16 + csel) * 2u;
                uint32_t af[2][4], bfr[4][4];
#pragma unroll
                for (int mt = 0; mt < 2; mt++)
                    ldsm4(ab + SWZ((uint32_t)(m0 + mt * 16 + rsel) * 128u + kc), af[mt]);
#pragma unroll
                for (int nt2 = 0; nt2 < 4; nt2++)
                    ldsm4(bb + SWZ((uint32_t)(n0 + nt2 * 16 + rsel) * 128u + kc), bfr[nt2]);
#pragma unroll
                for (int mt = 0; mt < 2; mt++)
#pragma unroll
                    for (int nt = 0; nt < 8; nt++)
                        mma_bf16(acc[mt][nt], af[mt],
                                 bfr[nt >> 1][nt & 1], bfr[nt >> 1][(nt & 1) + 2]);
            }
        }
    }

    // direct fragment store
    {
        int r = lane >> 2, cc = (lane & 3) * 2;
        float* dst = (E ? g_z : g_xspre) + (size_t)b * DD * LL + l0;
#pragma unroll
        for (int mt = 0; mt < 2; mt++)
#pragma unroll
            for (int nt = 0; nt < 8; nt++) {
                int l = m0 + mt * 16 + r;
                int e = n0 + nt * 8 + cc;
                dst[(size_t)e * LL + l]           = acc[mt][nt][0];
                dst[(size_t)(e + 1) * LL + l]     = acc[mt][nt][1];
                dst[(size_t)e * LL + l + 8]       = acc[mt][nt][2];
                dst[(size_t)(e + 1) * LL + l + 8] = acc[mt][nt][3];
            }
    }
}

// ================= K2: conv+silu, xproj, dt, local scan (64-token chunks) =================
#define PC 69
__global__ __launch_bounds__(256, 3) void k2_chunk(const float* __restrict__ conv_w,
                                                   const float* __restrict__ conv_b,
                                                   const float* __restrict__ W_xproj,
                                                   const float* __restrict__ W_dt,
                                                   const float* __restrict__ b_dt,
                                                   const float* __restrict__ A_log,
                                                   const float* __restrict__ D_param)
{
    extern __shared__ float sm[];
    float* sA    = sm;                      // [128][PC]
    float* sB    = sA + 128 * PC;           // [128][PC]
    float* sdbl  = sB + 128 * PC;           // [64][13]
    float* swc   = sdbl + 64 * 13;
    float* sbc   = swc + 512;
    float* swx   = sbc + 128;
    float* swd   = swx + 1536;
    float* sbd   = swd + 1024;

    const int tid = threadIdx.x;
    const int b = blockIdx.x >> 6;
    const int c = blockIdx.x & 63;
    const int l0 = c << 6;
    const float* src = g_xspre + (size_t)b * DD * LL;

    for (int j = tid; j < 128 * 67; j += 256) {
        int d = j / 67, i = j - d * 67;
        int idx = l0 - 3 + i;
        sA[d * PC + i] = (idx >= 0) ? src[(size_t)d * LL + idx] : 0.f;
    }
    for (int j = tid; j < 512; j += 256) swc[j] = conv_w[j];
    if (tid < 128) sbc[tid] = conv_b[tid];
    for (int j = tid; j < 1536; j += 256) swx[j] = W_xproj[j];
    for (int j = tid; j < 1024; j += 256) swd[j] = W_dt[j];
    if (tid < 128) sbd[tid] = b_dt[tid];
    __syncthreads();

    for (int j = tid; j < 128 * 64; j += 256) {
        int d = j >> 6, l = j & 63;
        float v = sbc[d];
        v += swc[d * 4 + 0] * sA[d * PC + l + 0];
        v += swc[d * 4 + 1] * sA[d * PC + l + 1];
        v += swc[d * 4 + 2] * sA[d * PC + l + 2];
        v += swc[d * 4 + 3] * sA[d * PC + l + 3];
        float sg = 1.f / (1.f + __expf(-v));
        sB[d * PC + l] = v * sg;
    }
    __syncthreads();

    for (int task = tid; task < 12 * 64; task += 256) {
        int jrow = task >> 6, l = task & 63;
        const float* wr = swx + jrow * 128;
        float s = 0.f;
#pragma unroll 8
        for (int d = 0; d < 128; d++) s += sB[d * PC + l] * wr[d];
        sdbl[l * 13 + jrow] = s;
    }
    __syncthreads();

    if (tid < 128) {
        int l = tid >> 1, n = tid & 1;
        g_Cm[((size_t)b * LL + l0 + l) * 2 + n] = sdbl[l * 13 + 10 + n];
    }

    for (int j = tid; j < 128 * 64; j += 256) {
        int d = j >> 6, l = j & 63;
        float v = sbd[d];
        const float* wr = swd + d * 8;
        const float* dr = sdbl + l * 13;
#pragma unroll
        for (int r = 0; r < 8; r++) v += dr[r] * wr[r];
        float sp = (v > 20.f) ? v : log1pf(__expf(v));
        sA[d * PC + l] = sp;
    }
    __syncthreads();

    {
        const int d = tid >> 1, n = tid & 1;
        const float An = -__expf(A_log[d * 2 + n]);
        const float Dd = D_param[d];
        float h = 0.f, sd = 0.f;
        for (int l = 0; l < 64; l++) {
            float dtv = sA[d * PC + l];
            sd += dtv;
            float xv = sB[d * PC + l];
            float Bn = sdbl[l * 13 + 8 + n];
            float Cn = sdbl[l * 13 + 10 + n];
            h = __expf(An * dtv) * h + dtv * Bn * xv;
            float yn = Cn * h;
            float yo = __shfl_xor_sync(0xffffffffu, yn, 1);
            if (n == 0) {
                sB[d * PC + l] = yn + yo + xv * Dd;
                sA[d * PC + l] = sd;
            }
        }
        size_t ci = (size_t)(b * NCH + c) * 128 + d;
        if (n == 0) g_sumdt[ci] = sd;
        g_hend[ci * 2 + n] = h;
    }
    __syncthreads();

    float* dS = g_S    + (size_t)b * DD * LL + l0;
    float* dY = g_yloc + (size_t)b * DD * LL + l0;
    for (int j = tid; j < 128 * 64; j += 256) {
        int d = j >> 6, l = j & 63;
        dS[(size_t)d * LL + l] = sA[d * PC + l];
        dY[(size_t)d * LL + l] = sB[d * PC + l];
    }
}

// ================= K2.5: chunk-summary scan =================
__global__ void k25_chainscan(const float* __restrict__ A_log)
{
    int t = blockIdx.x * 256 + threadIdx.x;
    if (t >= BB * DD) return;
    int b = t >> 7, d = t & 127;
    float A1 = -__expf(A_log[d * 2 + 0]);
    float A2 = -__expf(A_log[d * 2 + 1]);
    float h1 = 0.f, h2 = 0.f;
    for (int c = 0; c < NCH; c++) {
        size_t i = (size_t)(b * NCH + c) * 128 + d;
        g_h0[i * 2 + 0] = h1;
        g_h0[i * 2 + 1] = h2;
        float sd = g_sumdt[i];
        h1 = __expf(A1 * sd) * h1 + g_hend[i * 2 + 0];
        h2 = __expf(A2 * sd) * h2 + g_hend[i * 2 + 1];
    }
}

// ================= K3: finalize y, gate, out-proj, LayerNorm =================
#define K3_TAH 0
#define K3_TAL 8192
#define K3_TBH 16384
#define K3_TBL 32768
#define K3_EA  49152
#define K3_SG  50176
#define K3_SBv 50688
#define K3_MU  51200
#define K3_RS  51456
#define K3_SMEM 51712
#define PO 65

__global__ __launch_bounds__(128, 4) void k3_mma(const float* __restrict__ A_log,
                                                 const float* __restrict__ ln_g,
                                                 const float* __restrict__ ln_b,
                                                 float* __restrict__ out)
{
    extern __shared__ char smem[];
    const uint32_t sb = smem_u32(smem);
    const int tid = threadIdx.x, wid = tid >> 5, lane = tid & 31;
    const int b = blockIdx.x >> 6;
    const int c = blockIdx.x & 63;
    const int l0 = c << 6;
    const size_t base = (size_t)b * DD * LL + l0;

    float* eA  = (float*)(smem + K3_EA);
    float* sg  = (float*)(smem + K3_SG);
    float* sbv = (float*)(smem + K3_SBv);
    float* mu  = (float*)(smem + K3_MU);
    float* rs  = (float*)(smem + K3_RS);
    if (tid < 128) {
        eA[tid] = -__expf(A_log[tid]);
        eA[tid + 128] = -__expf(A_log[tid + 128]);
        sg[tid] = ln_g[tid]; sbv[tid] = ln_b[tid];
    }
    __syncthreads();

    const int m0 = (wid & 1) * 32, n0 = (wid >> 1) * 64;
    const int rsel = lane & 15;
    const int csel = (lane >> 4) * 8;

    float acc[2][8][4];
#pragma unroll
    for (int mt = 0; mt < 2; mt++)
#pragma unroll
        for (int nt = 0; nt < 8; nt++)
#pragma unroll
            for (int q = 0; q < 4; q++) acc[mt][nt][q] = 0.f;

#pragma unroll 1
    for (int h = 0; h < 2; h++) {
        const int d0 = h << 6;
        if (h) __syncthreads();
        // B half via cp.async (issue first so it overlaps A-stage math)
        {
            const uint4* pBh = gW3[h][0];
            const uint4* pBl = gW3[h][1];
#pragma unroll 8
            for (int j = tid; j < 1024; j += 128) {
                CP16(sb + K3_TBH + j * 16, pBh + j);
                CP16(sb + K3_TBL + j * 16, pBl + j);
            }
            CP_COMMIT();
        }
        // A half: gated y[l][d] computed
#pragma unroll 2
        for (int j = tid; j < 2048; j += 128) {
            int l = j & 63, dp = j >> 6, d = d0 + dp * 2;
            float2 C = *(const float2*)(g_Cm + ((size_t)b * LL + l0 + l) * 2);
            float yv[2];
#pragma unroll
            for (int q = 0; q < 2; q++) {
                int dd = d + q;
                size_t g = base + (size_t)dd * LL + l;
                float yl = g_yloc[g];
                float S  = g_S[g];
                float zv = g_z[g];
                size_t hi = (size_t)(b * NCH + c) * 128 + dd;
                float h01 = g_h0[hi * 2 + 0], h02 = g_h0[hi * 2 + 1];
                float A1 = eA[dd * 2 + 0], A2 = eA[dd * 2 + 1];
                float y = yl + C.x * __expf(A1 * S) * h01 + C.y * __expf(A2 * S) * h02;
                float sig = 1.f / (1.f + __expf(-zv));
                yv[q] = y * (zv * sig);
            }
            uint32_t hi32, lo32; split_pack(yv[0], yv[1], hi32, lo32);
            uint32_t off = SWZ((uint32_t)l * 128u + (uint32_t)dp * 4u);
            *(uint32_t*)(smem + K3_TAH + off) = hi32;
            *(uint32_t*)(smem + K3_TAL + off) = lo32;
        }
        CP_WAIT0();
        __syncthreads();

#pragma unroll 1
        for (int term = 0; term < 3; term++) {
            uint32_t ab = sb + (term == 2 ? K3_TAL : K3_TAH);
            uint32_t bb = sb + (term == 1 ? K3_TBL : K3_TBH);
#pragma unroll
            for (int ks = 0; ks < 4; ks++) {
                uint32_t kc = (uint32_t)(ks * 16 + csel) * 2u;
                uint32_t af[2][4], bfr[4][4];
#pragma unroll
                for (int mt = 0; mt < 2; mt++)
                    ldsm4(ab + SWZ((uint32_t)(m0 + mt * 16 + rsel) * 128u + kc), af[mt]);
#pragma unroll
                for (int nt2 = 0; nt2 < 4; nt2++)
                    ldsm4(bb + SWZ((uint32_t)(n0 + nt2 * 16 + rsel) * 128u + kc), bfr[nt2]);
#pragma unroll
                for (int mt = 0; mt < 2; mt++)
#pragma unroll
                    for (int nt = 0; nt < 8; nt++)
                        mma_bf16(acc[mt][nt], af[mt],
                                 bfr[nt >> 1][nt & 1], bfr[nt >> 1][(nt & 1) + 2]);
            }
        }
    }
    __syncthreads();

    // stage O[o][PO] f32 (overlays tiles)
    float* Os = (float*)smem;
    {
        int r = lane >> 2, cc = (lane & 3) * 2;
#pragma unroll
        for (int mt = 0; mt < 2; mt++)
#pragma unroll
            for (int nt = 0; nt < 8; nt++) {
                int l = m0 + mt * 16 + r, o = n0 + nt * 8 + cc;
                Os[o * PO + l]           = acc[mt][nt][0];
                Os[(o + 1) * PO + l]     = acc[mt][nt][1];
                Os[o * PO + l + 8]       = acc[mt][nt][2];
                Os[(o + 1) * PO + l + 8] = acc[mt][nt][3];
            }
    }
    __syncthreads();

    for (int l = wid; l < 64; l += 4) {
        float s = 0.f, s2 = 0.f;
#pragma unroll
        for (int o = lane; o < 128; o += 32) {
            float v = Os[o * PO + l];
            s += v; s2 += v * v;
        }
#pragma unroll
        for (int off = 16; off; off >>= 1) {
            s  += __shfl_xor_sync(0xffffffffu, s,  off);
            s2 += __shfl_xor_sync(0xffffffffu, s2, off);
        }
        if (lane == 0) {
            float m = s * (1.f / 128.f);
            mu[l] = m;
            rs[l] = rsqrtf(s2 * (1.f / 128.f) - m * m + 1e-5f);
        }
    }
    __syncthreads();

    float* op = out + base;
#pragma unroll 4
    for (int j = tid; j < 128 * 64; j += 128) {
        int o = j >> 6, l = j & 63;
        float v = (Os[o * PO + l] - mu[l]) * rs[l] * sg[o] + sbv[o];
        op[(size_t)o * LL + l] = v;
    }
}

// ---------------- launch ----------------
extern "C" void kernel_launch(void* const* d_in, const int* in_sizes, int n_in,
                              void* d_out, int out_size)
{
    const float* x1      = (const float*)d_in[0];
    const float* W_in    = (const float*)d_in[1];
    const float* conv_w  = (const float*)d_in[2];
    const float* conv_b  = (const float*)d_in[3];
    const float* W_xproj = (const float*)d_in[4];
    const float* W_dt    = (const float*)d_in[5];
    const float* b_dt    = (const float*)d_in[6];
    const float* A_log   = (const float*)d_in[7];
    const float* D_param = (const float*)d_in[8];
    const float* W_out   = (const float*)d_in[9];
    const float* ln_g    = (const float*)d_in[10];
    const float* ln_b    = (const float*)d_in[11];
    float* out = (float*)d_out;

    const int smem_k2 = (2 * 128 * PC + 64 * 13 + 512 + 128 + 1536 + 1024 + 128) * 4;

    static bool inited = false;
    if (!inited) {
        cudaFuncSetAttribute(k1_mma, cudaFuncAttributeMaxDynamicSharedMemorySize, K1_SMEM);
        cudaFuncSetAttribute(k2_chunk, cudaFuncAttributeMaxDynamicSharedMemorySize, smem_k2);
        cudaFuncSetAttribute(k3_mma, cudaFuncAttributeMaxDynamicSharedMemorySize, K3_SMEM);
        inited = true;
    }

    k0w<<<1, 256>>>(W_in, W_out);
    k0x<<<2048, 128>>>(x1);
    k1_mma<<<dim3(1024, 2), 128, K1_SMEM>>>();
    k2_chunk<<<1024, 256, smem_k2>>>(conv_w, conv_b, W_xproj, W_dt, b_dt, A_log, D_param);
    k25_chainscan<<<8, 256>>>(A_log);
    k3_mma<<<1024, 128, K3_SMEM>>>(A_log, ln_g, ln_b, out);
}

// round 13
// speedup vs baseline: 1.0376x; 1.0376x over previous
#include <cuda_runtime.h>
#include <cuda_bf16.h>
#include <math.h>
#include <stdint.h>

// Problem constants
#define BB 16
#define DD 128
#define LL 4096
#define NCH 64          // 64-token chunks per batch

// ---------------- scratch ----------------
__device__ float g_xspre[BB * DD * LL];
__device__ float g_z    [BB * DD * LL];
__device__ float g_S    [BB * DD * LL];
__device__ float g_yloc [BB * DD * LL];
__device__ float g_Cm   [BB * LL * 2];
__device__ float g_sumdt[BB * NCH * DD];
__device__ float g_hend [BB * NCH * DD * 2];
__device__ float g_h0   [BB * NCH * DD * 2];

// ---------------- helpers ----------------
__device__ __forceinline__ uint32_t smem_u32(const void* p) {
    uint32_t a;
    asm("{ .reg .u64 t; cvta.to.shared.u64 t, %1; cvt.u32.u64 %0, t; }" : "=r"(a) : "l"(p));
    return a;
}
__device__ __forceinline__ void ldsm4(uint32_t addr, uint32_t* r) {
    asm volatile("ldmatrix.sync.aligned.m8n8.x4.shared.b16 {%0,%1,%2,%3}, [%4];"
        : "=r"(r[0]), "=r"(r[1]), "=r"(r[2]), "=r"(r[3]) : "r"(addr));
}
__device__ __forceinline__ void mma_bf16(float* c, const uint32_t* a, uint32_t b0, uint32_t b1) {
    asm volatile("mma.sync.aligned.m16n8k16.row.col.f32.bf16.bf16.f32 "
        "{%0,%1,%2,%3}, {%4,%5,%6,%7}, {%8,%9}, {%0,%1,%2,%3};"
        : "+f"(c[0]), "+f"(c[1]), "+f"(c[2]), "+f"(c[3])
        : "r"(a[0]), "r"(a[1]), "r"(a[2]), "r"(a[3]), "r"(b0), "r"(b1));
}
__device__ __forceinline__ uint32_t pack_bf2(float a, float b) {
    __nv_bfloat16 ha = __float2bfloat16(a), hb = __float2bfloat16(b);
    return (uint32_t)__bfloat16_as_ushort(ha) | ((uint32_t)__bfloat16_as_ushort(hb) << 16);
}
__device__ __forceinline__ void split_pack(float v0, float v1, uint32_t& hi, uint32_t& lo) {
    __nv_bfloat16 h0 = __float2bfloat16(v0), h1 = __float2bfloat16(v1);
    hi = (uint32_t)__bfloat16_as_ushort(h0) | ((uint32_t)__bfloat16_as_ushort(h1) << 16);
    lo = pack_bf2(v0 - __bfloat162float(h0), v1 - __bfloat162float(h1));
}
#define SWZ(o) ((o) ^ ((((o) >> 7) & 7) << 4))

// ================= K1: xz = x @ W_in^T =================
// grid (1024, 2): 64 tokens x 128 outputs per block, 128 threads, 4 CTAs/SM
#define K1_TAH 0
#define K1_TAL 8192
#define K1_TBH 16384
#define K1_TBL 32768
#define K1_SMEM 49152

__global__ __launch_bounds__(128, 4) void k1_mma(const float* __restrict__ x1,
                                                 const float* __restrict__ W_in)
{
    extern __shared__ char smem[];
    const uint32_t sb = smem_u32(smem);
    const int tid = threadIdx.x, wid = tid >> 5, lane = tid & 31;
    const int b = blockIdx.x >> 6;
    const int l0 = (blockIdx.x & 63) << 6;
    const int ebase = blockIdx.y << 7;

    const int m0 = (wid & 1) * 32, n0 = (wid >> 1) * 64;
    const int rsel = lane & 15;
    const int csel = (lane >> 4) * 8;

    float acc[2][8][4];
#pragma unroll
    for (int mt = 0; mt < 2; mt++)
#pragma unroll
        for (int nt = 0; nt < 8; nt++)
#pragma unroll
            for (int q = 0; q < 4; q++) acc[mt][nt][q] = 0.f;

    const float* xb = x1 + (size_t)b * DD * LL;

#pragma unroll 1
    for (int h = 0; h < 2; h++) {
        const int d0 = h << 6;
        if (h) __syncthreads();
#pragma unroll 4
        for (int j = tid; j < 2048; j += 128) {
            int l = j & 63, dp = j >> 6, d = d0 + dp * 2;
            float v0 = xb[(size_t)d * LL + l0 + l];
            float v1 = xb[(size_t)(d + 1) * LL + l0 + l];
            uint32_t hi, lo; split_pack(v0, v1, hi, lo);
            uint32_t off = SWZ((uint32_t)l * 128u + (uint32_t)dp * 4u);
            *(uint32_t*)(smem + K1_TAH + off) = hi;
            *(uint32_t*)(smem + K1_TAL + off) = lo;
        }
#pragma unroll 4
        for (int j = tid; j < 4096; j += 128) {
            int eL = j >> 5, dp = j & 31, d = d0 + dp * 2;
            float2 w = *(const float2*)(W_in + (size_t)(ebase + eL) * 128 + d);
            uint32_t hi, lo; split_pack(w.x, w.y, hi, lo);
            uint32_t off = SWZ((uint32_t)eL * 128u + (uint32_t)dp * 4u);
            *(uint32_t*)(smem + K1_TBH + off) = hi;
            *(uint32_t*)(smem + K1_TBL + off) = lo;
        }
        __syncthreads();

#pragma unroll 1
        for (int term = 0; term < 3; term++) {
            uint32_t ab = sb + (term == 2 ? K1_TAL : K1_TAH);
            uint32_t bb = sb + (term == 1 ? K1_TBL : K1_TBH);
#pragma unroll
            for (int ks = 0; ks < 4; ks++) {
                uint32_t kc = (uint32_t)(ks * 16 + csel) * 2u;
                uint32_t af[2][4], bfr[4][4];
#pragma unroll
                for (int mt = 0; mt < 2; mt++)
                    ldsm4(ab + SWZ((uint32_t)(m0 + mt * 16 + rsel) * 128u + kc), af[mt]);
#pragma unroll
                for (int nt2 = 0; nt2 < 4; nt2++)
                    ldsm4(bb + SWZ((uint32_t)(n0 + nt2 * 16 + rsel) * 128u + kc), bfr[nt2]);
#pragma unroll
                for (int mt = 0; mt < 2; mt++)
#pragma unroll
                    for (int nt = 0; nt < 8; nt++)
                        mma_bf16(acc[mt][nt], af[mt],
                                 bfr[nt >> 1][nt & 1], bfr[nt >> 1][(nt & 1) + 2]);
            }
        }
    }

    {
        int r = lane >> 2, cc = (lane & 3) * 2;
        float* dst = (blockIdx.y ? g_z : g_xspre) + (size_t)b * DD * LL + l0;
#pragma unroll
        for (int mt = 0; mt < 2; mt++)
#pragma unroll
            for (int nt = 0; nt < 8; nt++) {
                int l = m0 + mt * 16 + r;
                int e = n0 + nt * 8 + cc;
                dst[(size_t)e * LL + l]           = acc[mt][nt][0];
                dst[(size_t)(e + 1) * LL + l]     = acc[mt][nt][1];
                dst[(size_t)e * LL + l + 8]       = acc[mt][nt][2];
                dst[(size_t)(e + 1) * LL + l + 8] = acc[mt][nt][3];
            }
    }
}

// ================= K2: conv+silu, xproj, dt, local scan (64-token chunks) =================
// smem: sA[128][67] (halo/dt/S), sB[128][65] (xs/y), sdbl[64][13]; weights via uniform LDG
#define PA 67
#define PB 65
#define K2_SMEM ((128 * PA + 128 * PB + 64 * 13) * 4)   // 70912

__global__ __launch_bounds__(256, 3) void k2_chunk(const float* __restrict__ conv_w,
                                                   const float* __restrict__ conv_b,
                                                   const float* __restrict__ W_xproj,
                                                   const float* __restrict__ W_dt,
                                                   const float* __restrict__ b_dt,
                                                   const float* __restrict__ A_log,
                                                   const float* __restrict__ D_param)
{
    extern __shared__ float sm[];
    float* sA   = sm;                       // [128][PA]
    float* sB   = sA + 128 * PA;            // [128][PB]
    float* sdbl = sB + 128 * PB;            // [64][13]

    const int tid = threadIdx.x;
    const int b = blockIdx.x >> 6;
    const int c = blockIdx.x & 63;
    const int l0 = c << 6;
    const float* src = g_xspre + (size_t)b * DD * LL;

    // halo-staged load: sA[d][i] = xs_pre[l0-3+i], coalesced along i
    for (int j = tid; j < 128 * 67; j += 256) {
        int d = j / 67, i = j - d * 67;
        int idx = l0 - 3 + i;
        sA[d * PA + i] = (idx >= 0) ? src[(size_t)d * LL + idx] : 0.f;
    }
    __syncthreads();

    // depthwise conv + silu -> sB (weights: warp-uniform LDG)
    for (int j = tid; j < 128 * 64; j += 256) {
        int d = j >> 6, l = j & 63;
        float4 w = *(const float4*)(conv_w + d * 4);
        float v = __ldg(conv_b + d);
        v += w.x * sA[d * PA + l + 0];
        v += w.y * sA[d * PA + l + 1];
        v += w.z * sA[d * PA + l + 2];
        v += w.w * sA[d * PA + l + 3];
        float sg = 1.f / (1.f + __expf(-v));
        sB[d * PB + l] = v * sg;
    }
    __syncthreads();

    // xproj: thread (g = jrow-group of 3, l); reuse each sB value for 3 rows
    {
        const int g = tid >> 6, l = tid & 63;
        const float* w0 = W_xproj + (3 * g + 0) * 128;
        const float* w1 = W_xproj + (3 * g + 1) * 128;
        const float* w2 = W_xproj + (3 * g + 2) * 128;
        float s0 = 0.f, s1 = 0.f, s2 = 0.f;
#pragma unroll 4
        for (int d4 = 0; d4 < 32; d4++) {
            float4 a = *(const float4*)(w0 + d4 * 4);
            float4 bq = *(const float4*)(w1 + d4 * 4);
            float4 cq = *(const float4*)(w2 + d4 * 4);
            float x0 = sB[(d4 * 4 + 0) * PB + l];
            float x1v = sB[(d4 * 4 + 1) * PB + l];
            float x2 = sB[(d4 * 4 + 2) * PB + l];
            float x3 = sB[(d4 * 4 + 3) * PB + l];
            s0 += a.x * x0 + a.y * x1v + a.z * x2 + a.w * x3;
            s1 += bq.x * x0 + bq.y * x1v + bq.z * x2 + bq.w * x3;
            s2 += cq.x * x0 + cq.y * x1v + cq.z * x2 + cq.w * x3;
        }
        sdbl[l * 13 + 3 * g + 0] = s0;
        sdbl[l * 13 + 3 * g + 1] = s1;
        sdbl[l * 13 + 3 * g + 2] = s2;
    }
    __syncthreads();

    // Cm out (tiny)
    if (tid < 128) {
        int l = tid >> 1, n = tid & 1;
        g_Cm[((size_t)b * LL + l0 + l) * 2 + n] = sdbl[l * 13 + 10 + n];
    }

    // dt: thread (q = d-quarter, l); dr in registers, uniform weight LDG
    {
        const int q = tid >> 6, l = tid & 63;
        float dr[8];
#pragma unroll
        for (int r = 0; r < 8; r++) dr[r] = sdbl[l * 13 + r];
#pragma unroll 4
        for (int dd = 0; dd < 32; dd++) {
            int d = q * 32 + dd;
            float4 wa = *(const float4*)(W_dt + d * 8);
            float4 wb = *(const float4*)(W_dt + d * 8 + 4);
            float v = __ldg(b_dt + d);
            v += wa.x * dr[0] + wa.y * dr[1] + wa.z * dr[2] + wa.w * dr[3];
            v += wb.x * dr[4] + wb.y * dr[5] + wb.z * dr[6] + wb.w * dr[7];
            float sp = (v > 20.f) ? v : log1pf(__expf(v));
            sA[d * PA + l] = sp;
        }
    }
    __syncthreads();

    // scan: one thread per channel, both states, no shfl
    if (tid < 128) {
        const int d = tid;
        const float A1 = -__expf(__ldg(A_log + 2 * d));
        const float A2 = -__expf(__ldg(A_log + 2 * d + 1));
        const float Dd = __ldg(D_param + d);
        float h1 = 0.f, h2 = 0.f, sd = 0.f;
#pragma unroll 4
        for (int l = 0; l < 64; l++) {
            float dtv = sA[d * PA + l];
            float xv  = sB[d * PB + l];
            float B1 = sdbl[l * 13 + 8],  B2 = sdbl[l * 13 + 9];
            float C1 = sdbl[l * 13 + 10], C2 = sdbl[l * 13 + 11];
            sd += dtv;
            float dx = dtv * xv;
            h1 = __expf(A1 * dtv) * h1 + dx * B1;
            h2 = __expf(A2 * dtv) * h2 + dx * B2;
            sB[d * PB + l] = C1 * h1 + C2 * h2 + xv * Dd;
            sA[d * PA + l] = sd;
        }
        size_t ci = (size_t)(b * NCH + c) * 128 + d;
        g_sumdt[ci] = sd;
        g_hend[ci * 2 + 0] = h1;
        g_hend[ci * 2 + 1] = h2;
    }
    __syncthreads();

    // flush S and y_local (coalesced)
    float* dS = g_S    + (size_t)b * DD * LL + l0;
    float* dY = g_yloc + (size_t)b * DD * LL + l0;
    for (int j = tid; j < 128 * 64; j += 256) {
        int d = j >> 6, l = j & 63;
        dS[(size_t)d * LL + l] = sA[d * PA + l];
        dY[(size_t)d * LL + l] = sB[d * PB + l];
    }
}

// ================= K2.5: chunk-summary scan =================
__global__ void k25_chainscan(const float* __restrict__ A_log)
{
    int t = blockIdx.x * 256 + threadIdx.x;
    if (t >= BB * DD) return;
    int b = t >> 7, d = t & 127;
    float A1 = -__expf(A_log[d * 2 + 0]);
    float A2 = -__expf(A_log[d * 2 + 1]);
    float h1 = 0.f, h2 = 0.f;
    for (int c = 0; c < NCH; c++) {
        size_t i = (size_t)(b * NCH + c) * 128 + d;
        g_h0[i * 2 + 0] = h1;
        g_h0[i * 2 + 1] = h2;
        float sd = g_sumdt[i];
        h1 = __expf(A1 * sd) * h1 + g_hend[i * 2 + 0];
        h2 = __expf(A2 * sd) * h2 + g_hend[i * 2 + 1];
    }
}

// ================= K3: finalize y, gate, out-proj, LayerNorm =================
#define K3_TAH 0
#define K3_TAL 8192
#define K3_TBH 16384
#define K3_TBL 32768
#define K3_EA  49152
#define K3_SG  50176
#define K3_SBv 50688
#define K3_MU  51200
#define K3_RS  51456
#define K3_H0  51712
#define K3_C   52736
#define K3_SMEM 53248
#define PO 65

__global__ __launch_bounds__(128, 4) void k3_mma(const float* __restrict__ W_out,
                                                 const float* __restrict__ A_log,
                                                 const float* __restrict__ ln_g,
                                                 const float* __restrict__ ln_b,
                                                 float* __restrict__ out)
{
    extern __shared__ char smem[];
    const uint32_t sb = smem_u32(smem);
    const int tid = threadIdx.x, wid = tid >> 5, lane = tid & 31;
    const int b = blockIdx.x >> 6;
    const int c = blockIdx.x & 63;
    const int l0 = c << 6;
    const size_t base = (size_t)b * DD * LL + l0;

    float* eA  = (float*)(smem + K3_EA);
    float* sg  = (float*)(smem + K3_SG);
    float* sbv = (float*)(smem + K3_SBv);
    float* mu  = (float*)(smem + K3_MU);
    float* rs  = (float*)(smem + K3_RS);
    float* sh0 = (float*)(smem + K3_H0);    // 256: h0[d][n]
    float* sC  = (float*)(smem + K3_C);     // 128: C[l][n]
    if (tid < 128) {
        eA[tid] = -__expf(A_log[tid]);
        eA[tid + 128] = -__expf(A_log[tid + 128]);
        sg[tid] = ln_g[tid]; sbv[tid] = ln_b[tid];
        float2 h0v = *(const float2*)(g_h0 + ((size_t)(b * NCH + c) * 128 + tid) * 2);
        sh0[tid * 2] = h0v.x; sh0[tid * 2 + 1] = h0v.y;
        if (tid < 64) {
            float2 Cv = *(const float2*)(g_Cm + ((size_t)b * LL + l0 + tid) * 2);
            sC[tid * 2] = Cv.x; sC[tid * 2 + 1] = Cv.y;
        }
    }
    __syncthreads();

    const int m0 = (wid & 1) * 32, n0 = (wid >> 1) * 64;
    const int rsel = lane & 15;
    const int csel = (lane >> 4) * 8;

    float acc[2][8][4];
#pragma unroll
    for (int mt = 0; mt < 2; mt++)
#pragma unroll
        for (int nt = 0; nt < 8; nt++)
#pragma unroll
            for (int q = 0; q < 4; q++) acc[mt][nt][q] = 0.f;

#pragma unroll 1
    for (int h = 0; h < 2; h++) {
        const int d0 = h << 6;
        if (h) __syncthreads();
        // A half: gated y[l][d]
#pragma unroll 2
        for (int j = tid; j < 2048; j += 128) {
            int l = j & 63, dp = j >> 6, d = d0 + dp * 2;
            float C1 = sC[l * 2], C2 = sC[l * 2 + 1];
            float yv[2];
#pragma unroll
            for (int q = 0; q < 2; q++) {
                int dd = d + q;
                size_t g = base + (size_t)dd * LL + l;
                float yl = g_yloc[g];
                float S  = g_S[g];
                float zv = g_z[g];
                float h01 = sh0[dd * 2], h02 = sh0[dd * 2 + 1];
                float A1 = eA[dd * 2 + 0], A2 = eA[dd * 2 + 1];
                float y = yl + C1 * __expf(A1 * S) * h01 + C2 * __expf(A2 * S) * h02;
                float sig = 1.f / (1.f + __expf(-zv));
                yv[q] = y * (zv * sig);
            }
            uint32_t hi32, lo32; split_pack(yv[0], yv[1], hi32, lo32);
            uint32_t off = SWZ((uint32_t)l * 128u + (uint32_t)dp * 4u);
            *(uint32_t*)(smem + K3_TAH + off) = hi32;
            *(uint32_t*)(smem + K3_TAL + off) = lo32;
        }
        // B half: W_out[o][d]
#pragma unroll 4
        for (int j = tid; j < 4096; j += 128) {
            int o = j >> 5, dp = j & 31, d = d0 + dp * 2;
            float2 w = *(const float2*)(W_out + (size_t)o * 128 + d);
            uint32_t hi32, lo32; split_pack(w.x, w.y, hi32, lo32);
            uint32_t off = SWZ((uint32_t)o * 128u + (uint32_t)dp * 4u);
            *(uint32_t*)(smem + K3_TBH + off) = hi32;
            *(uint32_t*)(smem + K3_TBL + off) = lo32;
        }
        __syncthreads();

#pragma unroll 1
        for (int term = 0; term < 3; term++) {
            uint32_t ab = sb + (term == 2 ? K3_TAL : K3_TAH);
            uint32_t bb = sb + (term == 1 ? K3_TBL : K3_TBH);
#pragma unroll
            for (int ks = 0; ks < 4; ks++) {
                uint32_t kc = (uint32_t)(ks * 16 + csel) * 2u;
                uint32_t af[2][4], bfr[4][4];
#pragma unroll
                for (int mt = 0; mt < 2; mt++)
                    ldsm4(ab + SWZ((uint32_t)(m0 + mt * 16 + rsel) * 128u + kc), af[mt]);
#pragma unroll
                for (int nt2 = 0; nt2 < 4; nt2++)
                    ldsm4(bb + SWZ((uint32_t)(n0 + nt2 * 16 + rsel) * 128u + kc), bfr[nt2]);
#pragma unroll
                for (int mt = 0; mt < 2; mt++)
#pragma unroll
                    for (int nt = 0; nt < 8; nt++)
                        mma_bf16(acc[mt][nt], af[mt],
                                 bfr[nt >> 1][nt & 1], bfr[nt >> 1][(nt & 1) + 2]);
            }
        }
    }
    __syncthreads();

    // stage O[o][PO] f32 (overlays tiles)
    float* Os = (float*)smem;
    {
        int r = lane >> 2, cc = (lane & 3) * 2;
#pragma unroll
        for (int mt = 0; mt < 2; mt++)
#pragma unroll
            for (int nt = 0; nt < 8; nt++) {
                int l = m0 + mt * 16 + r, o = n0 + nt * 8 + cc;
                Os[o * PO + l]           = acc[mt][nt][0];
                Os[(o + 1) * PO + l]     = acc[mt][nt][1];
                Os[o * PO + l + 8]       = acc[mt][nt][2];
                Os[(o + 1) * PO + l + 8] = acc[mt][nt][3];
            }
    }
    __syncthreads();

    for (int l = wid; l < 64; l += 4) {
        float s = 0.f, s2 = 0.f;
#pragma unroll
        for (int o = lane; o < 128; o += 32) {
            float v = Os[o * PO + l];
            s += v; s2 += v * v;
        }
#pragma unroll
        for (int off = 16; off; off >>= 1) {
            s  += __shfl_xor_sync(0xffffffffu, s,  off);
            s2 += __shfl_xor_sync(0xffffffffu, s2, off);
        }
        if (lane == 0) {
            float m = s * (1.f / 128.f);
            mu[l] = m;
            rs[l] = rsqrtf(s2 * (1.f / 128.f) - m * m + 1e-5f);
        }
    }
    __syncthreads();

    float* op = out + base;
#pragma unroll 4
    for (int j = tid; j < 128 * 64; j += 128) {
        int o = j >> 6, l = j & 63;
        float v = (Os[o * PO + l] - mu[l]) * rs[l] * sg[o] + sbv[o];
        op[(size_t)o * LL + l] = v;
    }
}

// ---------------- launch ----------------
extern "C" void kernel_launch(void* const* d_in, const int* in_sizes, int n_in,
                              void* d_out, int out_size)
{
    const float* x1      = (const float*)d_in[0];
    const float* W_in    = (const float*)d_in[1];
    const float* conv_w  = (const float*)d_in[2];
    const float* conv_b  = (const float*)d_in[3];
    const float* W_xproj = (const float*)d_in[4];
    const float* W_dt    = (const float*)d_in[5];
    const float* b_dt    = (const float*)d_in[6];
    const float* A_log   = (const float*)d_in[7];
    const float* D_param = (const float*)d_in[8];
    const float* W_out   = (const float*)d_in[9];
    const float* ln_g    = (const float*)d_in[10];
    const float* ln_b    = (const float*)d_in[11];
    float* out = (float*)d_out;

    static bool inited = false;
    if (!inited) {
        cudaFuncSetAttribute(k1_mma, cudaFuncAttributeMaxDynamicSharedMemorySize, K1_SMEM);
        cudaFuncSetAttribute(k2_chunk, cudaFuncAttributeMaxDynamicSharedMemorySize, K2_SMEM);
        cudaFuncSetAttribute(k3_mma, cudaFuncAttributeMaxDynamicSharedMemorySize, K3_SMEM);
        inited = true;
    }

    k1_mma<<<dim3(1024, 2), 128, K1_SMEM>>>(x1, W_in);
    k2_chunk<<<1024, 256, K2_SMEM>>>(conv_w, conv_b, W_xproj, W_dt, b_dt, A_log, D_param);
    k25_chainscan<<<8, 256>>>(A_log);
    k3_mma<<<1024, 128, K3_SMEM>>>(W_out, A_log, ln_g, ln_b, out);
}

// round 15
// speedup vs baseline: 1.1169x; 1.0764x over previous
#include <cuda_runtime.h>
#include <cuda_bf16.h>
#include <math.h>
#include <stdint.h>

// Problem constants
#define BB 16
#define DD 128
#define LL 4096
#define NCH 64          // 64-token chunks per batch

// ---------------- scratch ----------------
__device__ float g_xspre[BB * DD * LL];
__device__ float g_z    [BB * DD * LL];
__device__ float g_p    [BB * DD * LL];   // yloc * zsig
__device__ float g_q1   [BB * DD * LL];   // C1*exp(A1*S)*zsig
__device__ float g_q2   [BB * DD * LL];   // C2*exp(A2*S)*zsig
__device__ float g_sumdt[BB * NCH * DD];
__device__ float g_hend [BB * NCH * DD * 2];
__device__ float g_h0   [BB * NCH * DD * 2];

// pre-packed swizzled bf16 tiles: 16KB each
__device__ uint4 gW1[2][2][2][1024];   // W_in : [E-half][k-half][hi/lo]
__device__ uint4 gW3[2][2][1024];      // W_out: [k-half][hi/lo]

// ---------------- helpers ----------------
__device__ __forceinline__ uint32_t smem_u32(const void* p) {
    uint32_t a;
    asm("{ .reg .u64 t; cvta.to.shared.u64 t, %1; cvt.u32.u64 %0, t; }" : "=r"(a) : "l"(p));
    return a;
}
__device__ __forceinline__ void ldsm4(uint32_t addr, uint32_t* r) {
    asm volatile("ldmatrix.sync.aligned.m8n8.x4.shared.b16 {%0,%1,%2,%3}, [%4];"
        : "=r"(r[0]), "=r"(r[1]), "=r"(r[2]), "=r"(r[3]) : "r"(addr));
}
__device__ __forceinline__ void mma_bf16(float* c, const uint32_t* a, uint32_t b0, uint32_t b1) {
    asm volatile("mma.sync.aligned.m16n8k16.row.col.f32.bf16.bf16.f32 "
        "{%0,%1,%2,%3}, {%4,%5,%6,%7}, {%8,%9}, {%0,%1,%2,%3};"
        : "+f"(c[0]), "+f"(c[1]), "+f"(c[2]), "+f"(c[3])
        : "r"(a[0]), "r"(a[1]), "r"(a[2]), "r"(a[3]), "r"(b0), "r"(b1));
}
__device__ __forceinline__ uint32_t pack_bf2(float a, float b) {
    __nv_bfloat16 ha = __float2bfloat16(a), hb = __float2bfloat16(b);
    return (uint32_t)__bfloat16_as_ushort(ha) | ((uint32_t)__bfloat16_as_ushort(hb) << 16);
}
__device__ __forceinline__ void split_pack(float v0, float v1, uint32_t& hi, uint32_t& lo) {
    __nv_bfloat16 h0 = __float2bfloat16(v0), h1 = __float2bfloat16(v1);
    hi = (uint32_t)__bfloat16_as_ushort(h0) | ((uint32_t)__bfloat16_as_ushort(h1) << 16);
    lo = pack_bf2(v0 - __bfloat162float(h0), v1 - __bfloat162float(h1));
}
#define SWZ(o) ((o) ^ ((((o) >> 7) & 7) << 4))
#define CP16(dst, src) asm volatile("cp.async.cg.shared.global [%0], [%1], 16;" :: "r"(dst), "l"(src))
#define CP_COMMIT()  asm volatile("cp.async.commit_group;" ::: "memory")
#define CP_WAIT0()   asm volatile("cp.async.wait_group 0;" ::: "memory")

// ================= K0w: pack weights (parallel: 6 blocks) =================
__global__ __launch_bounds__(256) void k0w(const float* __restrict__ W_in,
                                           const float* __restrict__ W_out)
{
    const int tid = threadIdx.x, bid = blockIdx.x;
    if (bid < 4) {
        const int E = bid >> 1, kh = bid & 1;
        uint8_t* dhi = (uint8_t*)gW1[E][kh][0];
        uint8_t* dlo = (uint8_t*)gW1[E][kh][1];
        for (int j = tid; j < 128 * 32; j += 256) {
            int eL = j >> 5, dp = j & 31;
            float2 w = *(const float2*)(W_in + (size_t)(E * 128 + eL) * 128 + kh * 64 + dp * 2);
            uint32_t hi, lo; split_pack(w.x, w.y, hi, lo);
            uint32_t off = SWZ((uint32_t)eL * 128u + (uint32_t)dp * 4u);
            *(uint32_t*)(dhi + off) = hi;
            *(uint32_t*)(dlo + off) = lo;
        }
    } else {
        const int kh = bid - 4;
        uint8_t* dhi = (uint8_t*)gW3[kh][0];
        uint8_t* dlo = (uint8_t*)gW3[kh][1];
        for (int j = tid; j < 128 * 32; j += 256) {
            int o = j >> 5, dp = j & 31;
            float2 w = *(const float2*)(W_out + (size_t)o * 128 + kh * 64 + dp * 2);
            uint32_t hi, lo; split_pack(w.x, w.y, hi, lo);
            uint32_t off = SWZ((uint32_t)o * 128u + (uint32_t)dp * 4u);
            *(uint32_t*)(dhi + off) = hi;
            *(uint32_t*)(dlo + off) = lo;
        }
    }
}

// ================= K1: xz = x @ W_in^T =================
#define K1_TAH 0
#define K1_TAL 8192
#define K1_TBH 16384
#define K1_TBL 32768
#define K1_SMEM 49152

__global__ __launch_bounds__(128, 4) void k1_mma(const float* __restrict__ x1)
{
    extern __shared__ char smem[];
    const uint32_t sb = smem_u32(smem);
    const int tid = threadIdx.x, wid = tid >> 5, lane = tid & 31;
    const int b = blockIdx.x >> 6;
    const int l0 = (blockIdx.x & 63) << 6;
    const int E = blockIdx.y;

    const int m0 = (wid & 1) * 32, n0 = (wid >> 1) * 64;
    const int rsel = lane & 15;
    const int csel = (lane >> 4) * 8;

    float acc[2][8][4];
#pragma unroll
    for (int mt = 0; mt < 2; mt++)
#pragma unroll
        for (int nt = 0; nt < 8; nt++)
#pragma unroll
            for (int q = 0; q < 4; q++) acc[mt][nt][q] = 0.f;

    const float* xb = x1 + (size_t)b * DD * LL;

#pragma unroll 1
    for (int h = 0; h < 2; h++) {
        const int d0 = h << 6;
        if (h) __syncthreads();
        // B half via cp.async (overlaps A-stage compute)
        {
            const uint4* pBh = gW1[E][h][0];
            const uint4* pBl = gW1[E][h][1];
#pragma unroll 8
            for (int j = tid; j < 1024; j += 128) {
                CP16(sb + K1_TBH + j * 16, pBh + j);
                CP16(sb + K1_TBL + j * 16, pBl + j);
            }
            CP_COMMIT();
        }
        // A half: computed split
#pragma unroll 4
        for (int j = tid; j < 2048; j += 128) {
            int l = j & 63, dp = j >> 6, d = d0 + dp * 2;
            float v0 = xb[(size_t)d * LL + l0 + l];
            float v1 = xb[(size_t)(d + 1) * LL + l0 + l];
            uint32_t hi, lo; split_pack(v0, v1, hi, lo);
            uint32_t off = SWZ((uint32_t)l * 128u + (uint32_t)dp * 4u);
            *(uint32_t*)(smem + K1_TAH + off) = hi;
            *(uint32_t*)(smem + K1_TAL + off) = lo;
        }
        CP_WAIT0();
        __syncthreads();

#pragma unroll 1
        for (int term = 0; term < 3; term++) {
            uint32_t ab = sb + (term == 2 ? K1_TAL : K1_TAH);
            uint32_t bb = sb + (term == 1 ? K1_TBL : K1_TBH);
#pragma unroll
            for (int ks = 0; ks < 4; ks++) {
                uint32_t kc = (uint32_t)(ks * 16 + csel) * 2u;
                uint32_t af[2][4], bfr[4][4];
#pragma unroll
                for (int mt = 0; mt < 2; mt++)
                    ldsm4(ab + SWZ((uint32_t)(m0 + mt * 16 + rsel) * 128u + kc), af[mt]);
#pragma unroll
                for (int nt2 = 0; nt2 < 4; nt2++)
                    ldsm4(bb + SWZ((uint32_t)(n0 + nt2 * 16 + rsel) * 128u + kc), bfr[nt2]);
#pragma unroll
                for (int mt = 0; mt < 2; mt++)
#pragma unroll
                    for (int nt = 0; nt < 8; nt++)
                        mma_bf16(acc[mt][nt], af[mt],
                                 bfr[nt >> 1][nt & 1], bfr[nt >> 1][(nt & 1) + 2]);
            }
        }
    }

    {
        int r = lane >> 2, cc = (lane & 3) * 2;
        float* dst = (E ? g_z : g_xspre) + (size_t)b * DD * LL + l0;
#pragma unroll
        for (int mt = 0; mt < 2; mt++)
#pragma unroll
            for (int nt = 0; nt < 8; nt++) {
                int l = m0 + mt * 16 + r;
                int e = n0 + nt * 8 + cc;
                dst[(size_t)e * LL + l]           = acc[mt][nt][0];
                dst[(size_t)(e + 1) * LL + l]     = acc[mt][nt][1];
                dst[(size_t)e * LL + l + 8]       = acc[mt][nt][2];
                dst[(size_t)(e + 1) * LL + l + 8] = acc[mt][nt][3];
            }
    }
}

// ================= K2: conv+silu, xproj, dt, scan, gate-fold =================
#define PA 67
#define PB 65
#define K2_SMEM ((128 * PA + 128 * PB + 64 * 13 + 256) * 4)   // 71936

__global__ __launch_bounds__(256, 3) void k2_chunk(const float* __restrict__ conv_w,
                                                   const float* __restrict__ conv_b,
                                                   const float* __restrict__ W_xproj,
                                                   const float* __restrict__ W_dt,
                                                   const float* __restrict__ b_dt,
                                                   const float* __restrict__ A_log,
                                                   const float* __restrict__ D_param)
{
    extern __shared__ float sm[];
    float* sA   = sm;                       // [128][PA]
    float* sB   = sA + 128 * PA;            // [128][PB]
    float* sdbl = sB + 128 * PB;            // [64][13]
    float* seA  = sdbl + 64 * 13;           // [256] -exp(A_log)

    const int tid = threadIdx.x;
    const int b = blockIdx.x >> 6;
    const int c = blockIdx.x & 63;
    const int l0 = c << 6;
    const float* src = g_xspre + (size_t)b * DD * LL;

    if (tid < 128) {
        seA[2 * tid]     = -__expf(__ldg(A_log + 2 * tid));
        seA[2 * tid + 1] = -__expf(__ldg(A_log + 2 * tid + 1));
    }
    for (int j = tid; j < 128 * 67; j += 256) {
        int d = j / 67, i = j - d * 67;
        int idx = l0 - 3 + i;
        sA[d * PA + i] = (idx >= 0) ? src[(size_t)d * LL + idx] : 0.f;
    }
    __syncthreads();

    // depthwise conv + silu -> sB
    for (int j = tid; j < 128 * 64; j += 256) {
        int d = j >> 6, l = j & 63;
        float4 w = *(const float4*)(conv_w + d * 4);
        float v = __ldg(conv_b + d);
        v += w.x * sA[d * PA + l + 0];
        v += w.y * sA[d * PA + l + 1];
        v += w.z * sA[d * PA + l + 2];
        v += w.w * sA[d * PA + l + 3];
        float sg = 1.f / (1.f + __expf(-v));
        sB[d * PB + l] = v * sg;
    }
    __syncthreads();

    // xproj
    {
        const int g = tid >> 6, l = tid & 63;
        const float* w0 = W_xproj + (3 * g + 0) * 128;
        const float* w1 = W_xproj + (3 * g + 1) * 128;
        const float* w2 = W_xproj + (3 * g + 2) * 128;
        float s0 = 0.f, s1 = 0.f, s2 = 0.f;
#pragma unroll 4
        for (int d4 = 0; d4 < 32; d4++) {
            float4 a = *(const float4*)(w0 + d4 * 4);
            float4 bq = *(const float4*)(w1 + d4 * 4);
            float4 cq = *(const float4*)(w2 + d4 * 4);
            float x0 = sB[(d4 * 4 + 0) * PB + l];
            float x1v = sB[(d4 * 4 + 1) * PB + l];
            float x2 = sB[(d4 * 4 + 2) * PB + l];
            float x3 = sB[(d4 * 4 + 3) * PB + l];
            s0 += a.x * x0 + a.y * x1v + a.z * x2 + a.w * x3;
            s1 += bq.x * x0 + bq.y * x1v + bq.z * x2 + bq.w * x3;
            s2 += cq.x * x0 + cq.y * x1v + cq.z * x2 + cq.w * x3;
        }
        sdbl[l * 13 + 3 * g + 0] = s0;
        sdbl[l * 13 + 3 * g + 1] = s1;
        sdbl[l * 13 + 3 * g + 2] = s2;
    }
    __syncthreads();

    // dt -> sA
    {
        const int q = tid >> 6, l = tid & 63;
        float dr[8];
#pragma unroll
        for (int r = 0; r < 8; r++) dr[r] = sdbl[l * 13 + r];
#pragma unroll 4
        for (int dd = 0; dd < 32; dd++) {
            int d = q * 32 + dd;
            float4 wa = *(const float4*)(W_dt + d * 8);
            float4 wb = *(const float4*)(W_dt + d * 8 + 4);
            float v = __ldg(b_dt + d);
            v += wa.x * dr[0] + wa.y * dr[1] + wa.z * dr[2] + wa.w * dr[3];
            v += wb.x * dr[4] + wb.y * dr[5] + wb.z * dr[6] + wb.w * dr[7];
            float sp = (v > 20.f) ? v : log1pf(__expf(v));
            sA[d * PA + l] = sp;
        }
    }
    __syncthreads();

    // scan: one thread per channel, both states
    if (tid < 128) {
        const int d = tid;
        const float A1 = seA[2 * d], A2 = seA[2 * d + 1];
        const float Dd = __ldg(D_param + d);
        float h1 = 0.f, h2 = 0.f, sd = 0.f;
#pragma unroll 4
        for (int l = 0; l < 64; l++) {
            float dtv = sA[d * PA + l];
            float xv  = sB[d * PB + l];
            float B1 = sdbl[l * 13 + 8],  B2 = sdbl[l * 13 + 9];
            float C1 = sdbl[l * 13 + 10], C2 = sdbl[l * 13 + 11];
            sd += dtv;
            float dx = dtv * xv;
            h1 = __expf(A1 * dtv) * h1 + dx * B1;
            h2 = __expf(A2 * dtv) * h2 + dx * B2;
            sB[d * PB + l] = C1 * h1 + C2 * h2 + xv * Dd;
            sA[d * PA + l] = sd;
        }
        size_t ci = (size_t)(b * NCH + c) * 128 + d;
        g_sumdt[ci] = sd;
        g_hend[ci * 2 + 0] = h1;
        g_hend[ci * 2 + 1] = h2;
    }
    __syncthreads();

    // gate-fold flush: p = yloc*zsig ; q1 = C1*exp(A1*S)*zsig ; q2 = C2*exp(A2*S)*zsig
    const size_t base = (size_t)b * DD * LL + l0;
    const float* zsrc = g_z + base;
    float* dP  = g_p  + base;
    float* dQ1 = g_q1 + base;
    float* dQ2 = g_q2 + base;
    for (int j = tid; j < 128 * 64; j += 256) {
        int d = j >> 6, l = j & 63;
        float S  = sA[d * PA + l];
        float yl = sB[d * PB + l];
        float zv = zsrc[(size_t)d * LL + l];
        float zsig = zv / (1.f + __expf(-zv));
        float C1 = sdbl[l * 13 + 10], C2 = sdbl[l * 13 + 11];
        dP [(size_t)d * LL + l] = yl * zsig;
        dQ1[(size_t)d * LL + l] = C1 * __expf(seA[2 * d] * S) * zsig;
        dQ2[(size_t)d * LL + l] = C2 * __expf(seA[2 * d + 1] * S) * zsig;
    }
}

// ================= K2.5: chunk-summary scan =================
__global__ void k25_chainscan(const float* __restrict__ A_log)
{
    int t = blockIdx.x * 256 + threadIdx.x;
    if (t >= BB * DD) return;
    int b = t >> 7, d = t & 127;
    float A1 = -__expf(A_log[d * 2 + 0]);
    float A2 = -__expf(A_log[d * 2 + 1]);
    float h1 = 0.f, h2 = 0.f;
    for (int c = 0; c < NCH; c++) {
        size_t i = (size_t)(b * NCH + c) * 128 + d;
        g_h0[i * 2 + 0] = h1;
        g_h0[i * 2 + 1] = h2;
        float sd = g_sumdt[i];
        h1 = __expf(A1 * sd) * h1 + g_hend[i * 2 + 0];
        h2 = __expf(A2 * sd) * h2 + g_hend[i * 2 + 1];
    }
}

// ================= K3: y = p + q1*h01 + q2*h02 ; out-proj ; LayerNorm =================
#define K3_TAH 0
#define K3_TAL 8192
#define K3_TBH 16384
#define K3_TBL 32768
#define K3_SG  49152
#define K3_SBv 49664
#define K3_MU  50176
#define K3_RS  50432
#define K3_H0  50688
#define K3_SMEM 51712
#define PO 65

__global__ __launch_bounds__(128, 4) void k3_mma(const float* __restrict__ ln_g,
                                                 const float* __restrict__ ln_b,
                                                 float* __restrict__ out)
{
    extern __shared__ char smem[];
    const uint32_t sb = smem_u32(smem);
    const int tid = threadIdx.x, wid = tid >> 5, lane = tid & 31;
    const int b = blockIdx.x >> 6;
    const int c = blockIdx.x & 63;
    const int l0 = c << 6;
    const size_t base = (size_t)b * DD * LL + l0;

    float* sg  = (float*)(smem + K3_SG);
    float* sbv = (float*)(smem + K3_SBv);
    float* mu  = (float*)(smem + K3_MU);
    float* rs  = (float*)(smem + K3_RS);
    float* sh0 = (float*)(smem + K3_H0);    // 256: h0[d][n]
    if (tid < 128) {
        sg[tid] = __ldg(ln_g + tid); sbv[tid] = __ldg(ln_b + tid);
        float2 h0v = *(const float2*)(g_h0 + ((size_t)(b * NCH + c) * 128 + tid) * 2);
        sh0[tid * 2] = h0v.x; sh0[tid * 2 + 1] = h0v.y;
    }

    const int m0 = (wid & 1) * 32, n0 = (wid >> 1) * 64;
    const int rsel = lane & 15;
    const int csel = (lane >> 4) * 8;

    float acc[2][8][4];
#pragma unroll
    for (int mt = 0; mt < 2; mt++)
#pragma unroll
        for (int nt = 0; nt < 8; nt++)
#pragma unroll
            for (int q = 0; q < 4; q++) acc[mt][nt][q] = 0.f;

#pragma unroll 1
    for (int h = 0; h < 2; h++) {
        const int d0 = h << 6;
        __syncthreads();   // h=0: guards sh0 init; h=1: guards tile reuse
        // B half via cp.async
        {
            const uint4* pBh = gW3[h][0];
            const uint4* pBl = gW3[h][1];
#pragma unroll 8
            for (int j = tid; j < 1024; j += 128) {
                CP16(sb + K3_TBH + j * 16, pBh + j);
                CP16(sb + K3_TBL + j * 16, pBl + j);
            }
            CP_COMMIT();
        }
        // A half: y = p + q1*h01 + q2*h02
#pragma unroll 4
        for (int j = tid; j < 2048; j += 128) {
            int l = j & 63, dp = j >> 6, d = d0 + dp * 2;
            float yv[2];
#pragma unroll
            for (int q = 0; q < 2; q++) {
                int dd = d + q;
                size_t g = base + (size_t)dd * LL + l;
                yv[q] = g_p[g] + g_q1[g] * sh0[dd * 2] + g_q2[g] * sh0[dd * 2 + 1];
            }
            uint32_t hi32, lo32; split_pack(yv[0], yv[1], hi32, lo32);
            uint32_t off = SWZ((uint32_t)l * 128u + (uint32_t)dp * 4u);
            *(uint32_t*)(smem + K3_TAH + off) = hi32;
            *(uint32_t*)(smem + K3_TAL + off) = lo32;
        }
        CP_WAIT0();
        __syncthreads();

#pragma unroll 1
        for (int term = 0; term < 3; term++) {
            uint32_t ab = sb + (term == 2 ? K3_TAL : K3_TAH);
            uint32_t bb = sb + (term == 1 ? K3_TBL : K3_TBH);
#pragma unroll
            for (int ks = 0; ks < 4; ks++) {
                uint32_t kc = (uint32_t)(ks * 16 + csel) * 2u;
                uint32_t af[2][4], bfr[4][4];
#pragma unroll
                for (int mt = 0; mt < 2; mt++)
                    ldsm4(ab + SWZ((uint32_t)(m0 + mt * 16 + rsel) * 128u + kc), af[mt]);
#pragma unroll
                for (int nt2 = 0; nt2 < 4; nt2++)
                    ldsm4(bb + SWZ((uint32_t)(n0 + nt2 * 16 + rsel) * 128u + kc), bfr[nt2]);
#pragma unroll
                for (int mt = 0; mt < 2; mt++)
#pragma unroll
                    for (int nt = 0; nt < 8; nt++)
                        mma_bf16(acc[mt][nt], af[mt],
                                 bfr[nt >> 1][nt & 1], bfr[nt >> 1][(nt & 1) + 2]);
            }
        }
    }
    __syncthreads();

    // stage O[o][PO] f32 (overlays tiles)
    float* Os = (float*)smem;
    {
        int r = lane >> 2, cc = (lane & 3) * 2;
#pragma unroll
        for (int mt = 0; mt < 2; mt++)
#pragma unroll
            for (int nt = 0; nt < 8; nt++) {
                int l = m0 + mt * 16 + r, o = n0 + nt * 8 + cc;
                Os[o * PO + l]           = acc[mt][nt][0];
                Os[(o + 1) * PO + l]     = acc[mt][nt][1];
                Os[o * PO + l + 8]       = acc[mt][nt][2];
                Os[(o + 1) * PO + l + 8] = acc[mt][nt][3];
            }
    }
    __syncthreads();

    for (int l = wid; l < 64; l += 4) {
        float s = 0.f, s2 = 0.f;
#pragma unroll
        for (int o = lane; o < 128; o += 32) {
            float v = Os[o * PO + l];
            s += v; s2 += v * v;
        }
#pragma unroll
        for (int off = 16; off; off >>= 1) {
            s  += __shfl_xor_sync(0xffffffffu, s,  off);
            s2 += __shfl_xor_sync(0xffffffffu, s2, off);
        }
        if (lane == 0) {
            float m = s * (1.f / 128.f);
            mu[l] = m;
            rs[l] = rsqrtf(s2 * (1.f / 128.f) - m * m + 1e-5f);
        }
    }
    __syncthreads();

    float* op = out + base;
#pragma unroll 4
    for (int j = tid; j < 128 * 64; j += 128) {
        int o = j >> 6, l = j & 63;
        float v = (Os[o * PO + l] - mu[l]) * rs[l] * sg[o] + sbv[o];
        op[(size_t)o * LL + l] = v;
    }
}

// ---------------- launch ----------------
extern "C" void kernel_launch(void* const* d_in, const int* in_sizes, int n_in,
                              void* d_out, int out_size)
{
    const float* x1      = (const float*)d_in[0];
    const float* W_in    = (const float*)d_in[1];
    const float* conv_w  = (const float*)d_in[2];
    const float* conv_b  = (const float*)d_in[3];
    const float* W_xproj = (const float*)d_in[4];
    const float* W_dt    = (const float*)d_in[5];
    const float* b_dt    = (const float*)d_in[6];
    const float* A_log   = (const float*)d_in[7];
    const float* D_param = (const float*)d_in[8];
    const float* W_out   = (const float*)d_in[9];
    const float* ln_g    = (const float*)d_in[10];
    const float* ln_b    = (const float*)d_in[11];
    float* out = (float*)d_out;

    static bool inited = false;
    if (!inited) {
        cudaFuncSetAttribute(k1_mma, cudaFuncAttributeMaxDynamicSharedMemorySize, K1_SMEM);
        cudaFuncSetAttribute(k2_chunk, cudaFuncAttributeMaxDynamicSharedMemorySize, K2_SMEM);
        cudaFuncSetAttribute(k3_mma, cudaFuncAttributeMaxDynamicSharedMemorySize, K3_SMEM);
        inited = true;
    }

    k0w<<<6, 256>>>(W_in, W_out);
    k1_mma<<<dim3(1024, 2), 128, K1_SMEM>>>(x1);
    k2_chunk<<<1024, 256, K2_SMEM>>>(conv_w, conv_b, W_xproj, W_dt, b_dt, A_log, D_param);
    k25_chainscan<<<8, 256>>>(A_log);
    k3_mma<<<1024, 128, K3_SMEM>>>(ln_g, ln_b, out);
}

// round 17
// speedup vs baseline: 1.2251x; 1.0969x over previous
#include <cuda_runtime.h>
#include <cuda_bf16.h>
#include <math.h>
#include <stdint.h>

// Problem constants
#define BB 16
#define DD 128
#define LL 4096
#define NCH 64          // 64-token chunks per batch

// ---------------- scratch ----------------
__device__ float g_xspre[BB * DD * LL];
__device__ float g_z    [BB * DD * LL];
__device__ float g_p    [BB * DD * LL];   // yloc * zsig
__device__ float g_q1   [BB * DD * LL];   // C1*exp(A1*S)*zsig
__device__ float g_q2   [BB * DD * LL];   // C2*exp(A2*S)*zsig
__device__ float g_sumdt[BB * DD * NCH];          // [b][d][c]
__device__ float g_hend [BB * DD * NCH * 2];      // [b][d][c][n]
__device__ float g_h0   [BB * NCH * DD * 2];      // [b][c][d][n]  (K3-friendly)

// pre-packed swizzled bf16 tiles: 16KB each
__device__ uint4 gW1[2][2][2][1024];   // W_in : [E-half][k-half][hi/lo]
__device__ uint4 gW3[2][2][1024];      // W_out: [k-half][hi/lo]

// ---------------- helpers ----------------
__device__ __forceinline__ uint32_t smem_u32(const void* p) {
    uint32_t a;
    asm("{ .reg .u64 t; cvta.to.shared.u64 t, %1; cvt.u32.u64 %0, t; }" : "=r"(a) : "l"(p));
    return a;
}
__device__ __forceinline__ void ldsm4(uint32_t addr, uint32_t* r) {
    asm volatile("ldmatrix.sync.aligned.m8n8.x4.shared.b16 {%0,%1,%2,%3}, [%4];"
        : "=r"(r[0]), "=r"(r[1]), "=r"(r[2]), "=r"(r[3]) : "r"(addr));
}
__device__ __forceinline__ void mma_bf16(float* c, const uint32_t* a, uint32_t b0, uint32_t b1) {
    asm volatile("mma.sync.aligned.m16n8k16.row.col.f32.bf16.bf16.f32 "
        "{%0,%1,%2,%3}, {%4,%5,%6,%7}, {%8,%9}, {%0,%1,%2,%3};"
        : "+f"(c[0]), "+f"(c[1]), "+f"(c[2]), "+f"(c[3])
        : "r"(a[0]), "r"(a[1]), "r"(a[2]), "r"(a[3]), "r"(b0), "r"(b1));
}
__device__ __forceinline__ uint32_t pack_bf2(float a, float b) {
    __nv_bfloat16 ha = __float2bfloat16(a), hb = __float2bfloat16(b);
    return (uint32_t)__bfloat16_as_ushort(ha) | ((uint32_t)__bfloat16_as_ushort(hb) << 16);
}
__device__ __forceinline__ void split_pack(float v0, float v1, uint32_t& hi, uint32_t& lo) {
    __nv_bfloat16 h0 = __float2bfloat16(v0), h1 = __float2bfloat16(v1);
    hi = (uint32_t)__bfloat16_as_ushort(h0) | ((uint32_t)__bfloat16_as_ushort(h1) << 16);
    lo = pack_bf2(v0 - __bfloat162float(h0), v1 - __bfloat162float(h1));
}
#define SWZ(o) ((o) ^ ((((o) >> 7) & 7) << 4))
#define CP16(dst, src) asm volatile("cp.async.cg.shared.global [%0], [%1], 16;" :: "r"(dst), "l"(src))
#define CP_COMMIT()  asm volatile("cp.async.commit_group;" ::: "memory")
#define CP_WAIT0()   asm volatile("cp.async.wait_group 0;" ::: "memory")

// ================= K0w: pack weights (parallel: 6 blocks) =================
__global__ __launch_bounds__(256) void k0w(const float* __restrict__ W_in,
                                           const float* __restrict__ W_out)
{
    const int tid = threadIdx.x, bid = blockIdx.x;
    if (bid < 4) {
        const int E = bid >> 1, kh = bid & 1;
        uint8_t* dhi = (uint8_t*)gW1[E][kh][0];
        uint8_t* dlo = (uint8_t*)gW1[E][kh][1];
        for (int j = tid; j < 128 * 32; j += 256) {
            int eL = j >> 5, dp = j & 31;
            float2 w = *(const float2*)(W_in + (size_t)(E * 128 + eL) * 128 + kh * 64 + dp * 2);
            uint32_t hi, lo; split_pack(w.x, w.y, hi, lo);
            uint32_t off = SWZ((uint32_t)eL * 128u + (uint32_t)dp * 4u);
            *(uint32_t*)(dhi + off) = hi;
            *(uint32_t*)(dlo + off) = lo;
        }
    } else {
        const int kh = bid - 4;
        uint8_t* dhi = (uint8_t*)gW3[kh][0];
        uint8_t* dlo = (uint8_t*)gW3[kh][1];
        for (int j = tid; j < 128 * 32; j += 256) {
            int o = j >> 5, dp = j & 31;
            float2 w = *(const float2*)(W_out + (size_t)o * 128 + kh * 64 + dp * 2);
            uint32_t hi, lo; split_pack(w.x, w.y, hi, lo);
            uint32_t off = SWZ((uint32_t)o * 128u + (uint32_t)dp * 4u);
            *(uint32_t*)(dhi + off) = hi;
            *(uint32_t*)(dlo + off) = lo;
        }
    }
}

// ================= K1: xz = x @ W_in^T =================
#define K1_TAH 0
#define K1_TAL 8192
#define K1_TBH 16384
#define K1_TBL 32768
#define K1_SMEM 49152

__global__ __launch_bounds__(128, 4) void k1_mma(const float* __restrict__ x1)
{
    extern __shared__ char smem[];
    const uint32_t sb = smem_u32(smem);
    const int tid = threadIdx.x, wid = tid >> 5, lane = tid & 31;
    const int b = blockIdx.x >> 6;
    const int l0 = (blockIdx.x & 63) << 6;
    const int E = blockIdx.y;

    const int m0 = (wid & 1) * 32, n0 = (wid >> 1) * 64;
    const int rsel = lane & 15;
    const int csel = (lane >> 4) * 8;

    float acc[2][8][4];
#pragma unroll
    for (int mt = 0; mt < 2; mt++)
#pragma unroll
        for (int nt = 0; nt < 8; nt++)
#pragma unroll
            for (int q = 0; q < 4; q++) acc[mt][nt][q] = 0.f;

    const float* xb = x1 + (size_t)b * DD * LL;

#pragma unroll 1
    for (int h = 0; h < 2; h++) {
        const int d0 = h << 6;
        if (h) __syncthreads();
        // B half via cp.async (overlaps A-stage compute)
        {
            const uint4* pBh = gW1[E][h][0];
            const uint4* pBl = gW1[E][h][1];
#pragma unroll 8
            for (int j = tid; j < 1024; j += 128) {
                CP16(sb + K1_TBH + j * 16, pBh + j);
                CP16(sb + K1_TBL + j * 16, pBl + j);
            }
            CP_COMMIT();
        }
        // A half: computed split
#pragma unroll 4
        for (int j = tid; j < 2048; j += 128) {
            int l = j & 63, dp = j >> 6, d = d0 + dp * 2;
            float v0 = xb[(size_t)d * LL + l0 + l];
            float v1 = xb[(size_t)(d + 1) * LL + l0 + l];
            uint32_t hi, lo; split_pack(v0, v1, hi, lo);
            uint32_t off = SWZ((uint32_t)l * 128u + (uint32_t)dp * 4u);
            *(uint32_t*)(smem + K1_TAH + off) = hi;
            *(uint32_t*)(smem + K1_TAL + off) = lo;
        }
        CP_WAIT0();
        __syncthreads();

#pragma unroll 1
        for (int term = 0; term < 3; term++) {
            uint32_t ab = sb + (term == 2 ? K1_TAL : K1_TAH);
            uint32_t bb = sb + (term == 1 ? K1_TBL : K1_TBH);
#pragma unroll
            for (int ks = 0; ks < 4; ks++) {
                uint32_t kc = (uint32_t)(ks * 16 + csel) * 2u;
                uint32_t af[2][4], bfr[4][4];
#pragma unroll
                for (int mt = 0; mt < 2; mt++)
                    ldsm4(ab + SWZ((uint32_t)(m0 + mt * 16 + rsel) * 128u + kc), af[mt]);
#pragma unroll
                for (int nt2 = 0; nt2 < 4; nt2++)
                    ldsm4(bb + SWZ((uint32_t)(n0 + nt2 * 16 + rsel) * 128u + kc), bfr[nt2]);
#pragma unroll
                for (int mt = 0; mt < 2; mt++)
#pragma unroll
                    for (int nt = 0; nt < 8; nt++)
                        mma_bf16(acc[mt][nt], af[mt],
                                 bfr[nt >> 1][nt & 1], bfr[nt >> 1][(nt & 1) + 2]);
            }
        }
    }

    {
        int r = lane >> 2, cc = (lane & 3) * 2;
        float* dst = (E ? g_z : g_xspre) + (size_t)b * DD * LL + l0;
#pragma unroll
        for (int mt = 0; mt < 2; mt++)
#pragma unroll
            for (int nt = 0; nt < 8; nt++) {
                int l = m0 + mt * 16 + r;
                int e = n0 + nt * 8 + cc;
                dst[(size_t)e * LL + l]           = acc[mt][nt][0];
                dst[(size_t)(e + 1) * LL + l]     = acc[mt][nt][1];
                dst[(size_t)e * LL + l + 8]       = acc[mt][nt][2];
                dst[(size_t)(e + 1) * LL + l + 8] = acc[mt][nt][3];
            }
    }
}

// ================= K2: conv+silu, xproj, dt, scan, gate-fold =================
#define PA 67
#define PB 65
#define K2_SMEM ((128 * PA + 128 * PB + 64 * 13 + 256) * 4)   // 71936

__global__ __launch_bounds__(256, 3) void k2_chunk(const float* __restrict__ conv_w,
                                                   const float* __restrict__ conv_b,
                                                   const float* __restrict__ W_xproj,
                                                   const float* __restrict__ W_dt,
                                                   const float* __restrict__ b_dt,
                                                   const float* __restrict__ A_log,
                                                   const float* __restrict__ D_param)
{
    extern __shared__ float sm[];
    float* sA   = sm;                       // [128][PA]
    float* sB   = sA + 128 * PA;            // [128][PB]
    float* sdbl = sB + 128 * PB;            // [64][13]
    float* seA  = sdbl + 64 * 13;           // [256] -exp(A_log)

    const int tid = threadIdx.x;
    const int b = blockIdx.x >> 6;
    const int c = blockIdx.x & 63;
    const int l0 = c << 6;
    const float* src = g_xspre + (size_t)b * DD * LL;

    if (tid < 128) {
        seA[2 * tid]     = -__expf(__ldg(A_log + 2 * tid));
        seA[2 * tid + 1] = -__expf(__ldg(A_log + 2 * tid + 1));
    }
    for (int j = tid; j < 128 * 67; j += 256) {
        int d = j / 67, i = j - d * 67;
        int idx = l0 - 3 + i;
        sA[d * PA + i] = (idx >= 0) ? src[(size_t)d * LL + idx] : 0.f;
    }
    __syncthreads();

    // depthwise conv + silu -> sB
    for (int j = tid; j < 128 * 64; j += 256) {
        int d = j >> 6, l = j & 63;
        float4 w = *(const float4*)(conv_w + d * 4);
        float v = __ldg(conv_b + d);
        v += w.x * sA[d * PA + l + 0];
        v += w.y * sA[d * PA + l + 1];
        v += w.z * sA[d * PA + l + 2];
        v += w.w * sA[d * PA + l + 3];
        float sg = 1.f / (1.f + __expf(-v));
        sB[d * PB + l] = v * sg;
    }
    __syncthreads();

    // xproj
    {
        const int g = tid >> 6, l = tid & 63;
        const float* w0 = W_xproj + (3 * g + 0) * 128;
        const float* w1 = W_xproj + (3 * g + 1) * 128;
        const float* w2 = W_xproj + (3 * g + 2) * 128;
        float s0 = 0.f, s1 = 0.f, s2 = 0.f;
#pragma unroll 4
        for (int d4 = 0; d4 < 32; d4++) {
            float4 a = *(const float4*)(w0 + d4 * 4);
            float4 bq = *(const float4*)(w1 + d4 * 4);
            float4 cq = *(const float4*)(w2 + d4 * 4);
            float x0 = sB[(d4 * 4 + 0) * PB + l];
            float x1v = sB[(d4 * 4 + 1) * PB + l];
            float x2 = sB[(d4 * 4 + 2) * PB + l];
            float x3 = sB[(d4 * 4 + 3) * PB + l];
            s0 += a.x * x0 + a.y * x1v + a.z * x2 + a.w * x3;
            s1 += bq.x * x0 + bq.y * x1v + bq.z * x2 + bq.w * x3;
            s2 += cq.x * x0 + cq.y * x1v + cq.z * x2 + cq.w * x3;
        }
        sdbl[l * 13 + 3 * g + 0] = s0;
        sdbl[l * 13 + 3 * g + 1] = s1;
        sdbl[l * 13 + 3 * g + 2] = s2;
    }
    __syncthreads();

    // dt -> sA
    {
        const int q = tid >> 6, l = tid & 63;
        float dr[8];
#pragma unroll
        for (int r = 0; r < 8; r++) dr[r] = sdbl[l * 13 + r];
#pragma unroll 4
        for (int dd = 0; dd < 32; dd++) {
            int d = q * 32 + dd;
            float4 wa = *(const float4*)(W_dt + d * 8);
            float4 wb = *(const float4*)(W_dt + d * 8 + 4);
            float v = __ldg(b_dt + d);
            v += wa.x * dr[0] + wa.y * dr[1] + wa.z * dr[2] + wa.w * dr[3];
            v += wb.x * dr[4] + wb.y * dr[5] + wb.z * dr[6] + wb.w * dr[7];
            float sp = (v > 20.f) ? v : log1pf(__expf(v));
            sA[d * PA + l] = sp;
        }
    }
    __syncthreads();

    // scan: one thread per channel, both states
    if (tid < 128) {
        const int d = tid;
        const float A1 = seA[2 * d], A2 = seA[2 * d + 1];
        const float Dd = __ldg(D_param + d);
        float h1 = 0.f, h2 = 0.f, sd = 0.f;
#pragma unroll 4
        for (int l = 0; l < 64; l++) {
            float dtv = sA[d * PA + l];
            float xv  = sB[d * PB + l];
            float B1 = sdbl[l * 13 + 8],  B2 = sdbl[l * 13 + 9];
            float C1 = sdbl[l * 13 + 10], C2 = sdbl[l * 13 + 11];
            sd += dtv;
            float dx = dtv * xv;
            h1 = __expf(A1 * dtv) * h1 + dx * B1;
            h2 = __expf(A2 * dtv) * h2 + dx * B2;
            sB[d * PB + l] = C1 * h1 + C2 * h2 + xv * Dd;
            sA[d * PA + l] = sd;
        }
        // [b][d][c] layout for k25 vector loads
        size_t ci = ((size_t)b * 128 + d) * NCH + c;
        g_sumdt[ci] = sd;
        g_hend[ci * 2 + 0] = h1;
        g_hend[ci * 2 + 1] = h2;
    }
    __syncthreads();

    // gate-fold flush: p = yloc*zsig ; q1 = C1*exp(A1*S)*zsig ; q2 = C2*exp(A2*S)*zsig
    const size_t base = (size_t)b * DD * LL + l0;
    const float* zsrc = g_z + base;
    float* dP  = g_p  + base;
    float* dQ1 = g_q1 + base;
    float* dQ2 = g_q2 + base;
    for (int j = tid; j < 128 * 64; j += 256) {
        int d = j >> 6, l = j & 63;
        float S  = sA[d * PA + l];
        float yl = sB[d * PB + l];
        float zv = zsrc[(size_t)d * LL + l];
        float zsig = zv / (1.f + __expf(-zv));
        float C1 = sdbl[l * 13 + 10], C2 = sdbl[l * 13 + 11];
        dP [(size_t)d * LL + l] = yl * zsig;
        dQ1[(size_t)d * LL + l] = C1 * __expf(seA[2 * d] * S) * zsig;
        dQ2[(size_t)d * LL + l] = C2 * __expf(seA[2 * d + 1] * S) * zsig;
    }
}

// ================= K2.5: chunk-summary scan (vectorized, 32 blocks) =================
__global__ __launch_bounds__(64) void k25_chainscan(const float* __restrict__ A_log)
{
    const int t = blockIdx.x * 64 + threadIdx.x;   // t = b*128 + d, 2048 total
    const int b = t >> 7, d = t & 127;
    const float A1 = -__expf(__ldg(A_log + 2 * d));
    const float A2 = -__expf(__ldg(A_log + 2 * d + 1));
    float h1 = 0.f, h2 = 0.f;
    const size_t base = (size_t)t * NCH;
    const float4* ps = (const float4*)(g_sumdt + base);
    const float4* ph = (const float4*)(g_hend + base * 2);
#pragma unroll
    for (int c4 = 0; c4 < 16; c4++) {
        float4 sd = ps[c4];
        float4 e0 = ph[c4 * 2];
        float4 e1 = ph[c4 * 2 + 1];
        float sda[4] = {sd.x, sd.y, sd.z, sd.w};
        float heA[4] = {e0.x, e0.z, e1.x, e1.z};
        float heB[4] = {e0.y, e0.w, e1.y, e1.w};
#pragma unroll
        for (int q = 0; q < 4; q++) {
            int c = c4 * 4 + q;
            float* dst = g_h0 + (((size_t)(b * NCH + c)) * 128 + d) * 2;
            dst[0] = h1; dst[1] = h2;
            h1 = __expf(A1 * sda[q]) * h1 + heA[q];
            h2 = __expf(A2 * sda[q]) * h2 + heB[q];
        }
    }
}

// ================= K3: y = p + q1*h01 + q2*h02 ; out-proj ; LayerNorm =================
#define K3_TAH 0
#define K3_TAL 8192
#define K3_TBH 16384
#define K3_TBL 32768
#define K3_SG  49152
#define K3_SBv 49664
#define K3_MU  50176
#define K3_RS  50432
#define K3_H0  50688
#define K3_SMEM 51712
#define PO 65

__global__ __launch_bounds__(128, 4) void k3_mma(const float* __restrict__ ln_g,
                                                 const float* __restrict__ ln_b,
                                                 float* __restrict__ out)
{
    extern __shared__ char smem[];
    const uint32_t sb = smem_u32(smem);
    const int tid = threadIdx.x, wid = tid >> 5, lane = tid & 31;
    const int b = blockIdx.x >> 6;
    const int c = blockIdx.x & 63;
    const int l0 = c << 6;
    const size_t base = (size_t)b * DD * LL + l0;

    float* sg  = (float*)(smem + K3_SG);
    float* sbv = (float*)(smem + K3_SBv);
    float* mu  = (float*)(smem + K3_MU);
    float* rs  = (float*)(smem + K3_RS);
    float* sh0 = (float*)(smem + K3_H0);    // 256: h0[d][n]
    if (tid < 128) {
        sg[tid] = __ldg(ln_g + tid); sbv[tid] = __ldg(ln_b + tid);
        float2 h0v = *(const float2*)(g_h0 + ((size_t)(b * NCH + c) * 128 + tid) * 2);
        sh0[tid * 2] = h0v.x; sh0[tid * 2 + 1] = h0v.y;
    }

    const int m0 = (wid & 1) * 32, n0 = (wid >> 1) * 64;
    const int rsel = lane & 15;
    const int csel = (lane >> 4) * 8;

    float acc[2][8][4];
#pragma unroll
    for (int mt = 0; mt < 2; mt++)
#pragma unroll
        for (int nt = 0; nt < 8; nt++)
#pragma unroll
            for (int q = 0; q < 4; q++) acc[mt][nt][q] = 0.f;

#pragma unroll 1
    for (int h = 0; h < 2; h++) {
        const int d0 = h << 6;
        __syncthreads();   // h=0: guards sh0 init; h=1: guards tile reuse
        // B half via cp.async
        {
            const uint4* pBh = gW3[h][0];
            const uint4* pBl = gW3[h][1];
#pragma unroll 8
            for (int j = tid; j < 1024; j += 128) {
                CP16(sb + K3_TBH + j * 16, pBh + j);
                CP16(sb + K3_TBL + j * 16, pBl + j);
            }
            CP_COMMIT();
        }
        // A half: y = p + q1*h01 + q2*h02
#pragma unroll 4
        for (int j = tid; j < 2048; j += 128) {
            int l = j & 63, dp = j >> 6, d = d0 + dp * 2;
            float yv[2];
#pragma unroll
            for (int q = 0; q < 2; q++) {
                int dd = d + q;
                size_t g = base + (size_t)dd * LL + l;
                yv[q] = g_p[g] + g_q1[g] * sh0[dd * 2] + g_q2[g] * sh0[dd * 2 + 1];
            }
            uint32_t hi32, lo32; split_pack(yv[0], yv[1], hi32, lo32);
            uint32_t off = SWZ((uint32_t)l * 128u + (uint32_t)dp * 4u);
            *(uint32_t*)(smem + K3_TAH + off) = hi32;
            *(uint32_t*)(smem + K3_TAL + off) = lo32;
        }
        CP_WAIT0();
        __syncthreads();

#pragma unroll 1
        for (int term = 0; term < 3; term++) {
            uint32_t ab = sb + (term == 2 ? K3_TAL : K3_TAH);
            uint32_t bb = sb + (term == 1 ? K3_TBL : K3_TBH);
#pragma unroll
            for (int ks = 0; ks < 4; ks++) {
                uint32_t kc = (uint32_t)(ks * 16 + csel) * 2u;
                uint32_t af[2][4], bfr[4][4];
#pragma unroll
                for (int mt = 0; mt < 2; mt++)
                    ldsm4(ab + SWZ((uint32_t)(m0 + mt * 16 + rsel) * 128u + kc), af[mt]);
#pragma unroll
                for (int nt2 = 0; nt2 < 4; nt2++)
                    ldsm4(bb + SWZ((uint32_t)(n0 + nt2 * 16 + rsel) * 128u + kc), bfr[nt2]);
#pragma unroll
                for (int mt = 0; mt < 2; mt++)
#pragma unroll
                    for (int nt = 0; nt < 8; nt++)
                        mma_bf16(acc[mt][nt], af[mt],
                                 bfr[nt >> 1][nt & 1], bfr[nt >> 1][(nt & 1) + 2]);
            }
        }
    }
    __syncthreads();

    // stage O[o][PO] f32 (overlays tiles)
    float* Os = (float*)smem;
    {
        int r = lane >> 2, cc = (lane & 3) * 2;
#pragma unroll
        for (int mt = 0; mt < 2; mt++)
#pragma unroll
            for (int nt = 0; nt < 8; nt++) {
                int l = m0 + mt * 16 + r, o = n0 + nt * 8 + cc;
                Os[o * PO + l]           = acc[mt][nt][0];
                Os[(o + 1) * PO + l]     = acc[mt][nt][1];
                Os[o * PO + l + 8]       = acc[mt][nt][2];
                Os[(o + 1) * PO + l + 8] = acc[mt][nt][3];
            }
    }
    __syncthreads();

    for (int l = wid; l < 64; l += 4) {
        float s = 0.f, s2 = 0.f;
#pragma unroll
        for (int o = lane; o < 128; o += 32) {
            float v = Os[o * PO + l];
            s += v; s2 += v * v;
        }
#pragma unroll
        for (int off = 16; off; off >>= 1) {
            s  += __shfl_xor_sync(0xffffffffu, s,  off);
            s2 += __shfl_xor_sync(0xffffffffu, s2, off);
        }
        if (lane == 0) {
            float m = s * (1.f / 128.f);
            mu[l] = m;
            rs[l] = rsqrtf(s2 * (1.f / 128.f) - m * m + 1e-5f);
        }
    }
    __syncthreads();

    float* op = out + base;
#pragma unroll 4
    for (int j = tid; j < 128 * 64; j += 128) {
        int o = j >> 6, l = j & 63;
        float v = (Os[o * PO + l] - mu[l]) * rs[l] * sg[o] + sbv[o];
        op[(size_t)o * LL + l] = v;
    }
}

// ---------------- launch ----------------
extern "C" void kernel_launch(void* const* d_in, const int* in_sizes, int n_in,
                              void* d_out, int out_size)
{
    const float* x1      = (const float*)d_in[0];
    const float* W_in    = (const float*)d_in[1];
    const float* conv_w  = (const float*)d_in[2];
    const float* conv_b  = (const float*)d_in[3];
    const float* W_xproj = (const float*)d_in[4];
    const float* W_dt    = (const float*)d_in[5];
    const float* b_dt    = (const float*)d_in[6];
    const float* A_log   = (const float*)d_in[7];
    const float* D_param = (const float*)d_in[8];
    const float* W_out   = (const float*)d_in[9];
    const float* ln_g    = (const float*)d_in[10];
    const float* ln_b    = (const float*)d_in[11];
    float* out = (float*)d_out;

    static bool inited = false;
    if (!inited) {
        cudaFuncSetAttribute(k1_mma, cudaFuncAttributeMaxDynamicSharedMemorySize, K1_SMEM);
        cudaFuncSetAttribute(k2_chunk, cudaFuncAttributeMaxDynamicSharedMemorySize, K2_SMEM);
        cudaFuncSetAttribute(k3_mma, cudaFuncAttributeMaxDynamicSharedMemorySize, K3_SMEM);
        inited = true;
    }

    k0w<<<6, 256>>>(W_in, W_out);
    k1_mma<<<dim3(1024, 2), 128, K1_SMEM>>>(x1);
    k2_chunk<<<1024, 256, K2_SMEM>>>(conv_w, conv_b, W_xproj, W_dt, b_dt, A_log, D_param);
    k25_chainscan<<<32, 64>>>(A_log);
    k3_mma<<<1024, 128, K3_SMEM>>>(ln_g, ln_b, out);
}